// round 14
// baseline (speedup 1.0000x reference)
#include <cuda_runtime.h>
#include <math.h>
#include <stdint.h>

#define MTOT 8192
#define CDIM 1024
#define NHEAD 16
#define DH 64
#define TSEQ 2048

// Scratch (allocation-free rule: __device__ globals)
__device__ float g_Q[(size_t)MTOT * CDIM];
__device__ float g_V[(size_t)MTOT * CDIM];
__device__ float g_O[(size_t)MTOT * CDIM];

__device__ __forceinline__ float f2tf32f(float v) {
    uint32_t r;
    asm("cvt.rna.tf32.f32 %0, %1;" : "=r"(r) : "f"(v));
    return __uint_as_float(r);
}
__device__ __forceinline__ uint32_t f2tf32u(float v) {
    uint32_t r;
    asm("cvt.rna.tf32.f32 %0, %1;" : "=r"(r) : "f"(v));
    return r;
}

#define MMA_TF32(acc, a, b)                                                    \
    asm volatile(                                                              \
        "mma.sync.aligned.m16n8k8.row.col.f32.tf32.tf32.f32 "                  \
        "{%0,%1,%2,%3}, {%4,%5,%6,%7}, {%8,%9}, {%0,%1,%2,%3};"                \
        : "+f"((acc)[0]), "+f"((acc)[1]), "+f"((acc)[2]), "+f"((acc)[3])       \
        : "r"((a)[0]), "r"((a)[1]), "r"((a)[2]), "r"((a)[3]),                  \
          "r"((b).x), "r"((b).y))

// ===========================================================================
// tf32 mma.sync GEMM v2:  C[M,N] = A[M,K] @ B[N,K]^T
// CTA tile 128x256, BK=32, 256 threads = 8 warps (2M x 4N), warp tile 64x64.
// Fragment-reuse re-tile: each A-frag feeds 8 MMAs, each B-frag 4
// (176 B smem traffic per MMA vs 312 in the 64x32-warp version).
// SMEM pre-permuted into m16n8k8 fragment order; double buffered.
//   A buffer: [mt(8)][ks(4)][lane(32)][4]  = 4096 f
//   B buffer: [nt(32)][ks(4)][lane(32)][2] = 8192 f
// ===========================================================================
#define NCH (CDIM / 32)                   // 32 chunks
#define GEMM_SMEM (2 * 12288 * 4)         // 96 KB

__global__ __launch_bounds__(256, 1) void gemm_mma(
    const float* __restrict__ A, const float* __restrict__ B,
    float* __restrict__ C)
{
    extern __shared__ float smem[];
    const int tid = threadIdx.x;
    const int lane = tid & 31;
    const int wid = tid >> 5;
    const int wm = wid & 1;      // 0..1 (M, 64 rows each)
    const int wn = wid >> 1;     // 0..3 (N, 64 cols each)
    const int row0 = blockIdx.y * 128;
    const int col0 = blockIdx.x * 256;

    float acc[4][8][4];
#pragma unroll
    for (int i = 0; i < 4; i++)
#pragma unroll
        for (int j = 0; j < 8; j++)
#pragma unroll
            for (int r = 0; r < 4; r++) acc[i][j][r] = 0.f;

    // Loader: thread covers k-span [lk,lk+4); A rows lrow+32i (i<4),
    // B rows lrow+32i (i<8)
    const int lrow = tid >> 3;          // 0..31
    const int lk   = (tid & 7) << 2;    // 0..28
    const int ksA  = lk >> 3;           // 0..3
    const int regHi = (lk >> 2) & 1;

    const float* Ab = A + (size_t)(row0 + lrow) * CDIM + lk;
    const float* Bb = B + (size_t)(col0 + lrow) * CDIM + lk;

    float4 ra[4], rb[8];

#define STORE_CHUNK(buf) do {                                                  \
    float* Abuf = smem + (buf) * 12288;                                        \
    float* Bbuf = Abuf + 4096;                                                 \
    _Pragma("unroll")                                                          \
    for (int i = 0; i < 4; i++) {                                              \
        int r = i * 32 + lrow;                                                 \
        int mt = r >> 4, rm = r & 15;                                          \
        float* da = &Abuf[(((mt * 4 + ksA) * 32) + ((rm & 7) << 2)) * 4        \
                          + ((rm >> 3) | (regHi << 1))];                       \
        da[0]  = f2tf32f(ra[i].x); da[4]  = f2tf32f(ra[i].y);                  \
        da[8]  = f2tf32f(ra[i].z); da[12] = f2tf32f(ra[i].w);                  \
    }                                                                          \
    _Pragma("unroll")                                                          \
    for (int i = 0; i < 8; i++) {                                              \
        int r = i * 32 + lrow;                                                 \
        int nt = r >> 3, nn = r & 7;                                           \
        float* db = &Bbuf[(((nt * 4 + ksA) * 32) + (nn << 2)) * 2 + regHi];    \
        db[0] = f2tf32f(rb[i].x); db[2] = f2tf32f(rb[i].y);                    \
        db[4] = f2tf32f(rb[i].z); db[6] = f2tf32f(rb[i].w);                    \
    }                                                                          \
} while (0)

    // Prologue: chunk 0
#pragma unroll
    for (int i = 0; i < 4; i++)
        ra[i] = *(const float4*)(Ab + (size_t)(i * 32) * CDIM);
#pragma unroll
    for (int i = 0; i < 8; i++)
        rb[i] = *(const float4*)(Bb + (size_t)(i * 32) * CDIM);
    STORE_CHUNK(0);
    __syncthreads();

    for (int c = 0; c < NCH; c++) {
        const int cur = c & 1;
        if (c + 1 < NCH) {
#pragma unroll
            for (int i = 0; i < 4; i++)
                ra[i] = *(const float4*)(Ab + (size_t)(i * 32) * CDIM + (c + 1) * 32);
#pragma unroll
            for (int i = 0; i < 8; i++)
                rb[i] = *(const float4*)(Bb + (size_t)(i * 32) * CDIM + (c + 1) * 32);
        }

        const float* Abuf = smem + cur * 12288;
        const float* Bbuf = Abuf + 4096;
#pragma unroll
        for (int ks = 0; ks < 4; ks++) {
            uint4 af[4]; uint2 bf[8];
#pragma unroll
            for (int i = 0; i < 4; i++)
                af[i] = *(const uint4*)&Abuf[(((wm * 4 + i) * 4 + ks) * 32 + lane) * 4];
#pragma unroll
            for (int j = 0; j < 8; j++)
                bf[j] = *(const uint2*)&Bbuf[(((wn * 8 + j) * 4 + ks) * 32 + lane) * 2];
#pragma unroll
            for (int i = 0; i < 4; i++)
#pragma unroll
                for (int j = 0; j < 8; j++)
                    asm volatile(
                        "mma.sync.aligned.m16n8k8.row.col.f32.tf32.tf32.f32 "
                        "{%0,%1,%2,%3}, {%4,%5,%6,%7}, {%8,%9}, {%0,%1,%2,%3};"
                        : "+f"(acc[i][j][0]), "+f"(acc[i][j][1]),
                          "+f"(acc[i][j][2]), "+f"(acc[i][j][3])
                        : "r"(af[i].x), "r"(af[i].y), "r"(af[i].z), "r"(af[i].w),
                          "r"(bf[j].x), "r"(bf[j].y));
        }

        if (c + 1 < NCH) STORE_CHUNK((c + 1) & 1);
        __syncthreads();
    }

    // Epilogue: c0,c1 -> row = grp; c2,c3 -> row+8; cols = 2*tig + {0,1}
    const int grp = lane >> 2, tig = lane & 3;
#pragma unroll
    for (int i = 0; i < 4; i++) {
        int r = row0 + wm * 64 + i * 16 + grp;
#pragma unroll
        for (int j = 0; j < 8; j++) {
            int cc = col0 + wn * 64 + j * 8 + (tig << 1);
            *(float2*)(C + (size_t)r * CDIM + cc) =
                make_float2(acc[i][j][0], acc[i][j][1]);
            *(float2*)(C + (size_t)(r + 8) * CDIM + cc) =
                make_float2(acc[i][j][2], acc[i][j][3]);
        }
    }
#undef STORE_CHUNK
}

// ===========================================================================
// Tensorized flash attention v2 (unchanged from R11 WIN).
// CTA = 128 queries, 8 warps (16 rows each), 64-key tiles, Dh=64.
// K tile == Q tile data (ref bug: K uses W_q). Causal.
// ===========================================================================
#define ATT_SMEM (2 * 8192 * 4)

__global__ __launch_bounds__(256, 2) void attn_mma(
    const float* __restrict__ Q, const float* __restrict__ V,
    float* __restrict__ O)
{
    extern __shared__ float sm[];
    const int tid = threadIdx.x;
    const int lane = tid & 31, w = tid >> 5;
    const int grp = lane >> 2, tig = lane & 3;
    const int qb = (int)gridDim.x - 1 - (int)blockIdx.x;  // longest first
    const int bh = blockIdx.y;
    const int b = bh >> 4, h = bh & 15;
    const int t0 = qb * 128;

    const float* Qbase = Q + (size_t)b * TSEQ * CDIM + h * DH;
    const float* Vbase = V + (size_t)b * TSEQ * CDIM + h * DH;

    const int row0g = t0 + w * 16 + grp;
    const int row1g = row0g + 8;
    const int wrow_max = t0 + w * 16 + 15;

    uint32_t qa[8][4];
    {
        const float* q0 = Qbase + (size_t)row0g * CDIM;
        const float* q1 = Qbase + (size_t)row1g * CDIM;
#pragma unroll
        for (int ks = 0; ks < 8; ks++) {
            qa[ks][0] = f2tf32u(q0[ks * 8 + tig]);
            qa[ks][1] = f2tf32u(q1[ks * 8 + tig]);
            qa[ks][2] = f2tf32u(q0[ks * 8 + tig + 4]);
            qa[ks][3] = f2tf32u(q1[ks * 8 + tig + 4]);
        }
    }

    float oacc[8][4];
#pragma unroll
    for (int nt = 0; nt < 8; nt++)
#pragma unroll
        for (int r = 0; r < 4; r++) oacc[nt][r] = 0.f;
    float m0 = -1e30f, m1 = -1e30f, l0 = 0.f, l1 = 0.f;

    const float scale = 0.125f;
    const int ntiles = 2 * qb + 2;

#define LOAD_KV(j0, buf) do {                                                  \
    float* Kb_ = &sm[(buf) * 8192];                                            \
    float* Vb_ = Kb_ + 4096;                                                   \
    _Pragma("unroll")                                                          \
    for (int i = 0; i < 4; i++) {                                              \
        int idx = i * 256 + tid;                                               \
        int r = idx >> 4, c = (idx & 15) << 2;                                 \
        float4 k4 = *(const float4*)(Qbase + (size_t)((j0) + r) * CDIM + c);   \
        float4 v4 = *(const float4*)(Vbase + (size_t)((j0) + r) * CDIM + c);   \
        float* kb = &Kb_[(((r >> 3) * 8 + (c >> 3)) * 32                       \
                          + ((r & 7) << 2)) * 2 + ((c >> 2) & 1)];             \
        kb[0] = f2tf32f(k4.x); kb[2] = f2tf32f(k4.y);                          \
        kb[4] = f2tf32f(k4.z); kb[6] = f2tf32f(k4.w);                          \
        float* vb = &Vb_[(((c >> 3) * 8 + (r >> 3)) * 32                       \
                          + ((c & 7) << 2) + (r & 3)) * 2 + ((r >> 2) & 1)];   \
        vb[0]  = f2tf32f(v4.x); vb[8]  = f2tf32f(v4.y);                        \
        vb[16] = f2tf32f(v4.z); vb[24] = f2tf32f(v4.w);                        \
    }                                                                          \
} while (0)

    LOAD_KV(0, 0);

    for (int jt = 0; jt < ntiles; jt++) {
        const int j0 = jt * 64;
        __syncthreads();
        if (jt + 1 < ntiles) LOAD_KV((jt + 1) * 64, (jt + 1) & 1);

        if (j0 <= wrow_max) {
            const float* Kb = &sm[(jt & 1) * 8192];
            const float* Vb = Kb + 4096;

            float sc[8][4];
#pragma unroll
            for (int nt = 0; nt < 8; nt++) {
                sc[nt][0] = 0.f; sc[nt][1] = 0.f; sc[nt][2] = 0.f; sc[nt][3] = 0.f;
#pragma unroll
                for (int ks = 0; ks < 8; ks++) {
                    uint2 kb = *(const uint2*)&Kb[((nt * 8 + ks) * 32 + lane) * 2];
                    MMA_TF32(sc[nt], qa[ks], kb);
                }
            }

#pragma unroll
            for (int nt = 0; nt < 8; nt++) {
                sc[nt][0] *= scale; sc[nt][1] *= scale;
                sc[nt][2] *= scale; sc[nt][3] *= scale;
            }
            if (j0 + 63 > row0g) {
#pragma unroll
                for (int nt = 0; nt < 8; nt++) {
                    int c = j0 + nt * 8 + (tig << 1);
                    if (c > row0g)     sc[nt][0] = -1e30f;
                    if (c + 1 > row0g) sc[nt][1] = -1e30f;
                    if (c > row1g)     sc[nt][2] = -1e30f;
                    if (c + 1 > row1g) sc[nt][3] = -1e30f;
                }
            }

            float mx0 = -1e30f, mx1 = -1e30f;
#pragma unroll
            for (int nt = 0; nt < 8; nt++) {
                mx0 = fmaxf(mx0, fmaxf(sc[nt][0], sc[nt][1]));
                mx1 = fmaxf(mx1, fmaxf(sc[nt][2], sc[nt][3]));
            }
            mx0 = fmaxf(mx0, __shfl_xor_sync(0xffffffffu, mx0, 1));
            mx0 = fmaxf(mx0, __shfl_xor_sync(0xffffffffu, mx0, 2));
            mx1 = fmaxf(mx1, __shfl_xor_sync(0xffffffffu, mx1, 1));
            mx1 = fmaxf(mx1, __shfl_xor_sync(0xffffffffu, mx1, 2));

            float mn0 = fmaxf(m0, mx0), mn1 = fmaxf(m1, mx1);
            float al0 = __expf(m0 - mn0), al1 = __expf(m1 - mn1);
            m0 = mn0; m1 = mn1;

            float ps0 = 0.f, ps1 = 0.f;
#pragma unroll
            for (int nt = 0; nt < 8; nt++) {
                sc[nt][0] = __expf(sc[nt][0] - mn0);
                sc[nt][1] = __expf(sc[nt][1] - mn0);
                sc[nt][2] = __expf(sc[nt][2] - mn1);
                sc[nt][3] = __expf(sc[nt][3] - mn1);
                ps0 += sc[nt][0] + sc[nt][1];
                ps1 += sc[nt][2] + sc[nt][3];
            }
            ps0 += __shfl_xor_sync(0xffffffffu, ps0, 1);
            ps0 += __shfl_xor_sync(0xffffffffu, ps0, 2);
            ps1 += __shfl_xor_sync(0xffffffffu, ps1, 1);
            ps1 += __shfl_xor_sync(0xffffffffu, ps1, 2);
            l0 = l0 * al0 + ps0;
            l1 = l1 * al1 + ps1;

#pragma unroll
            for (int nt = 0; nt < 8; nt++) {
                oacc[nt][0] *= al0; oacc[nt][1] *= al0;
                oacc[nt][2] *= al1; oacc[nt][3] *= al1;
            }

            const int sL = tig >> 1;
            const bool odd = tig & 1;
#pragma unroll
            for (int ks = 0; ks < 8; ks++) {
                float a0 = __shfl_sync(0xffffffffu, sc[ks][0], sL, 4);
                float a1 = __shfl_sync(0xffffffffu, sc[ks][1], sL, 4);
                float b0 = __shfl_sync(0xffffffffu, sc[ks][0], sL + 2, 4);
                float b1 = __shfl_sync(0xffffffffu, sc[ks][1], sL + 2, 4);
                float c0 = __shfl_sync(0xffffffffu, sc[ks][2], sL, 4);
                float c1 = __shfl_sync(0xffffffffu, sc[ks][3], sL, 4);
                float d0 = __shfl_sync(0xffffffffu, sc[ks][2], sL + 2, 4);
                float d1 = __shfl_sync(0xffffffffu, sc[ks][3], sL + 2, 4);
                uint32_t pa[4];
                pa[0] = f2tf32u(odd ? a1 : a0);
                pa[1] = f2tf32u(odd ? c1 : c0);
                pa[2] = f2tf32u(odd ? b1 : b0);
                pa[3] = f2tf32u(odd ? d1 : d0);
#pragma unroll
                for (int nt = 0; nt < 8; nt++) {
                    uint2 vb = *(const uint2*)&Vb[((nt * 8 + ks) * 32 + lane) * 2];
                    MMA_TF32(oacc[nt], pa, vb);
                }
            }
        }
    }
#undef LOAD_KV

    float inv0 = 1.f / l0, inv1 = 1.f / l1;
    float* Ob = O + (size_t)b * TSEQ * CDIM + h * DH;
#pragma unroll
    for (int nt = 0; nt < 8; nt++) {
        int cc = nt * 8 + (tig << 1);
        *(float2*)(Ob + (size_t)row0g * CDIM + cc) =
            make_float2(oacc[nt][0] * inv0, oacc[nt][1] * inv0);
        *(float2*)(Ob + (size_t)row1g * CDIM + cc) =
            make_float2(oacc[nt][2] * inv1, oacc[nt][3] * inv1);
    }
}

// ---------------------------------------------------------------------------
extern "C" void kernel_launch(void* const* d_in, const int* in_sizes, int n_in,
                              void* d_out, int out_size)
{
    (void)in_sizes; (void)n_in; (void)out_size;
    const float* x  = (const float*)d_in[0];
    const float* Wq = (const float*)d_in[1];
    // d_in[2] (W_k) intentionally unused: reference computes K with W_q
    const float* Wv = (const float*)d_in[3];
    const float* Wo = (const float*)d_in[4];
    float* out = (float*)d_out;

    float *Qb, *Vb, *Ob;
    cudaGetSymbolAddress((void**)&Qb, g_Q);
    cudaGetSymbolAddress((void**)&Vb, g_V);
    cudaGetSymbolAddress((void**)&Ob, g_O);

    cudaFuncSetAttribute(gemm_mma, cudaFuncAttributeMaxDynamicSharedMemorySize,
                         GEMM_SMEM);
    cudaFuncSetAttribute(attn_mma, cudaFuncAttributeMaxDynamicSharedMemorySize,
                         ATT_SMEM);

    dim3 gg(CDIM / 256, MTOT / 128);  // (4, 64)
    gemm_mma<<<gg, 256, GEMM_SMEM>>>(x, Wq, Qb);
    gemm_mma<<<gg, 256, GEMM_SMEM>>>(x, Wv, Vb);

    attn_mma<<<dim3(TSEQ / 128, 4 * NHEAD), 256, ATT_SMEM>>>(Qb, Vb, Ob);

    gemm_mma<<<gg, 256, GEMM_SMEM>>>(Ob, Wo, out);
}

// round 15
// speedup vs baseline: 1.8019x; 1.8019x over previous
#include <cuda_runtime.h>
#include <math.h>
#include <stdint.h>

#define MTOT 8192
#define CDIM 1024
#define NHEAD 16
#define DH 64
#define TSEQ 2048

// Scratch (allocation-free rule: __device__ globals)
__device__ float g_Q [(size_t)MTOT * CDIM];   // Q  (row-major, attn input)
__device__ float g_V [(size_t)MTOT * CDIM];   // V  (row-major, attn input)
__device__ float g_Xp[(size_t)MTOT * CDIM];   // x   in A-fragment layout (tf32)
__device__ float g_Op[(size_t)MTOT * CDIM];   // attn out in A-fragment layout
__device__ float g_Wqp[(size_t)CDIM * CDIM];  // W_q in B-fragment layout (tf32)
__device__ float g_Wvp[(size_t)CDIM * CDIM];
__device__ float g_Wop[(size_t)CDIM * CDIM];

__device__ __forceinline__ float f2tf32f(float v) {
    uint32_t r;
    asm("cvt.rna.tf32.f32 %0, %1;" : "=r"(r) : "f"(v));
    return __uint_as_float(r);
}
__device__ __forceinline__ uint32_t f2tf32u(float v) {
    uint32_t r;
    asm("cvt.rna.tf32.f32 %0, %1;" : "=r"(r) : "f"(v));
    return r;
}

#define MMA_TF32(acc, a, b)                                                    \
    asm volatile(                                                              \
        "mma.sync.aligned.m16n8k8.row.col.f32.tf32.tf32.f32 "                  \
        "{%0,%1,%2,%3}, {%4,%5,%6,%7}, {%8,%9}, {%0,%1,%2,%3};"                \
        : "+f"((acc)[0]), "+f"((acc)[1]), "+f"((acc)[2]), "+f"((acc)[3])       \
        : "r"((a)[0]), "r"((a)[1]), "r"((a)[2]), "r"((a)[3]),                  \
          "r"((b).x), "r"((b).y))

// ===========================================================================
// Fragment layouts (128-row/col block granularity, 32 chunks of K=32):
//  A: [mblock][chunk][ (mt*4+ks)*32 + lane ]*4 + reg   (4096 f per block-chunk)
//     lane = (m&7)*4 + (k&3), reg = (m>>3 & 1) | ((k>>2 & 1)<<1)
//  B: [nblock][chunk][ (nt*4+ks)*32 + lane ]*2 + reg
//     lane = (n&7)*4 + (k&3), reg = (k>>2 & 1)
// ===========================================================================

// ---- pre-permute W[n][k] (row-major) -> B-fragment layout, tf32 ----------
__global__ __launch_bounds__(256) void perm_w(
    const float* __restrict__ W, float* __restrict__ Wp)
{
    int g = blockIdx.x * 256 + threadIdx.x;       // 0 .. 262143
    int n = g >> 8;
    int k = (g & 255) << 2;
    float4 w4 = *(const float4*)(W + (size_t)n * CDIM + k);
    int cb = n >> 7, chunk = k >> 5, ks = (k >> 3) & 3, regHi = (k >> 2) & 1;
    int nt = (n >> 3) & 15, nn = n & 7;
    float* d = Wp + ((size_t)(cb * 32 + chunk)) * 4096
                 + ((((nt * 4 + ks) * 32) + (nn << 2)) << 1) + regHi;
    d[0] = f2tf32f(w4.x); d[2] = f2tf32f(w4.y);
    d[4] = f2tf32f(w4.z); d[6] = f2tf32f(w4.w);
}

// ---- pre-permute X[row][k] (row-major) -> A-fragment layout, tf32 --------
__global__ __launch_bounds__(256) void perm_x(
    const float* __restrict__ X, float* __restrict__ Xp)
{
    int g = blockIdx.x * 256 + threadIdx.x;       // 0 .. 2097151
    int row = g >> 8;
    int k = (g & 255) << 2;
    float4 a4 = *(const float4*)(X + (size_t)row * CDIM + k);
    int mtile = row >> 7, r = row & 127, mt = r >> 4, rm = r & 15;
    int chunk = k >> 5, ks = (k >> 3) & 3, regHi = (k >> 2) & 1;
    float* d = Xp + ((size_t)(mtile * 32 + chunk)) * 4096
                 + ((((mt * 4 + ks) * 32) + ((rm & 7) << 2)) << 2)
                 + ((rm >> 3) | (regHi << 1));
    d[0] = f2tf32f(a4.x); d[4]  = f2tf32f(a4.y);
    d[8] = f2tf32f(a4.z); d[12] = f2tf32f(a4.w);
}

// ===========================================================================
// Zero-smem fragment-streaming GEMM: C[M,N] = A @ B^T, operands pre-permuted.
// CTA 128x128, 8 warps (2M x 4N), warp tile 64x32. No barriers at all.
// ===========================================================================
__global__ __launch_bounds__(256, 2) void gemm_frag(
    const float* __restrict__ Ap, const float* __restrict__ Bp,
    float* __restrict__ C)
{
    const int tid = threadIdx.x;
    const int lane = tid & 31;
    const int wid = tid >> 5;
    const int wm = wid & 1;      // 0..1 (M, 64 rows)
    const int wn = wid >> 1;     // 0..3 (N, 32 cols)

    const float* Abase = Ap + (size_t)blockIdx.y * 32 * 4096;
    const float* Bbase = Bp + (size_t)blockIdx.x * 32 * 4096;

    float acc[4][4][4];
#pragma unroll
    for (int i = 0; i < 4; i++)
#pragma unroll
        for (int j = 0; j < 4; j++)
#pragma unroll
            for (int r = 0; r < 4; r++) acc[i][j][r] = 0.f;

    for (int c = 0; c < 32; c++) {
        const float* Ac = Abase + (size_t)c * 4096;
        const float* Bc = Bbase + (size_t)c * 4096;
#pragma unroll
        for (int ks = 0; ks < 4; ks++) {
            uint4 af[4]; uint2 bf[4];
#pragma unroll
            for (int i = 0; i < 4; i++)
                af[i] = *(const uint4*)&Ac[(((wm * 16 + i * 4 + ks) * 32 + lane) << 2)];
#pragma unroll
            for (int j = 0; j < 4; j++)
                bf[j] = *(const uint2*)&Bc[(((wn * 16 + j * 4 + ks) * 32 + lane) << 1)];
#pragma unroll
            for (int i = 0; i < 4; i++)
#pragma unroll
                for (int j = 0; j < 4; j++)
                    asm volatile(
                        "mma.sync.aligned.m16n8k8.row.col.f32.tf32.tf32.f32 "
                        "{%0,%1,%2,%3}, {%4,%5,%6,%7}, {%8,%9}, {%0,%1,%2,%3};"
                        : "+f"(acc[i][j][0]), "+f"(acc[i][j][1]),
                          "+f"(acc[i][j][2]), "+f"(acc[i][j][3])
                        : "r"(af[i].x), "r"(af[i].y), "r"(af[i].z), "r"(af[i].w),
                          "r"(bf[j].x), "r"(bf[j].y));
        }
    }

    const int grp = lane >> 2, tig = lane & 3;
    const int row0 = blockIdx.y * 128, col0 = blockIdx.x * 128;
#pragma unroll
    for (int i = 0; i < 4; i++) {
        int r = row0 + wm * 64 + i * 16 + grp;
#pragma unroll
        for (int j = 0; j < 4; j++) {
            int cc = col0 + wn * 32 + j * 8 + (tig << 1);
            *(float2*)(C + (size_t)r * CDIM + cc) =
                make_float2(acc[i][j][0], acc[i][j][1]);
            *(float2*)(C + (size_t)(r + 8) * CDIM + cc) =
                make_float2(acc[i][j][2], acc[i][j][3]);
        }
    }
}

// ===========================================================================
// Tensorized flash attention (R11 WIN, unchanged) except the epilogue now
// writes the output directly into A-fragment layout (g_Op) for the O-proj.
// CTA = 128 queries, 8 warps, 64-key tiles. K tile == Q tile (ref bug).
// ===========================================================================
#define ATT_SMEM (2 * 8192 * 4)

__global__ __launch_bounds__(256, 2) void attn_mma(
    const float* __restrict__ Q, const float* __restrict__ V,
    float* __restrict__ Op)
{
    extern __shared__ float sm[];
    const int tid = threadIdx.x;
    const int lane = tid & 31, w = tid >> 5;
    const int grp = lane >> 2, tig = lane & 3;
    const int qb = (int)gridDim.x - 1 - (int)blockIdx.x;  // longest first
    const int bh = blockIdx.y;
    const int b = bh >> 4, h = bh & 15;
    const int t0 = qb * 128;

    const float* Qbase = Q + (size_t)b * TSEQ * CDIM + h * DH;
    const float* Vbase = V + (size_t)b * TSEQ * CDIM + h * DH;

    const int row0g = t0 + w * 16 + grp;
    const int row1g = row0g + 8;
    const int wrow_max = t0 + w * 16 + 15;

    uint32_t qa[8][4];
    {
        const float* q0 = Qbase + (size_t)row0g * CDIM;
        const float* q1 = Qbase + (size_t)row1g * CDIM;
#pragma unroll
        for (int ks = 0; ks < 8; ks++) {
            qa[ks][0] = f2tf32u(q0[ks * 8 + tig]);
            qa[ks][1] = f2tf32u(q1[ks * 8 + tig]);
            qa[ks][2] = f2tf32u(q0[ks * 8 + tig + 4]);
            qa[ks][3] = f2tf32u(q1[ks * 8 + tig + 4]);
        }
    }

    float oacc[8][4];
#pragma unroll
    for (int nt = 0; nt < 8; nt++)
#pragma unroll
        for (int r = 0; r < 4; r++) oacc[nt][r] = 0.f;
    float m0 = -1e30f, m1 = -1e30f, l0 = 0.f, l1 = 0.f;

    const float scale = 0.125f;
    const int ntiles = 2 * qb + 2;

#define LOAD_KV(j0, buf) do {                                                  \
    float* Kb_ = &sm[(buf) * 8192];                                            \
    float* Vb_ = Kb_ + 4096;                                                   \
    _Pragma("unroll")                                                          \
    for (int i = 0; i < 4; i++) {                                              \
        int idx = i * 256 + tid;                                               \
        int r = idx >> 4, c = (idx & 15) << 2;                                 \
        float4 k4 = *(const float4*)(Qbase + (size_t)((j0) + r) * CDIM + c);   \
        float4 v4 = *(const float4*)(Vbase + (size_t)((j0) + r) * CDIM + c);   \
        float* kb = &Kb_[(((r >> 3) * 8 + (c >> 3)) * 32                       \
                          + ((r & 7) << 2)) * 2 + ((c >> 2) & 1)];             \
        kb[0] = f2tf32f(k4.x); kb[2] = f2tf32f(k4.y);                          \
        kb[4] = f2tf32f(k4.z); kb[6] = f2tf32f(k4.w);                          \
        float* vb = &Vb_[(((c >> 3) * 8 + (r >> 3)) * 32                       \
                          + ((c & 7) << 2) + (r & 3)) * 2 + ((r >> 2) & 1)];   \
        vb[0]  = f2tf32f(v4.x); vb[8]  = f2tf32f(v4.y);                        \
        vb[16] = f2tf32f(v4.z); vb[24] = f2tf32f(v4.w);                        \
    }                                                                          \
} while (0)

    LOAD_KV(0, 0);

    for (int jt = 0; jt < ntiles; jt++) {
        const int j0 = jt * 64;
        __syncthreads();
        if (jt + 1 < ntiles) LOAD_KV((jt + 1) * 64, (jt + 1) & 1);

        if (j0 <= wrow_max) {
            const float* Kb = &sm[(jt & 1) * 8192];
            const float* Vb = Kb + 4096;

            float sc[8][4];
#pragma unroll
            for (int nt = 0; nt < 8; nt++) {
                sc[nt][0] = 0.f; sc[nt][1] = 0.f; sc[nt][2] = 0.f; sc[nt][3] = 0.f;
#pragma unroll
                for (int ks = 0; ks < 8; ks++) {
                    uint2 kb = *(const uint2*)&Kb[((nt * 8 + ks) * 32 + lane) * 2];
                    MMA_TF32(sc[nt], qa[ks], kb);
                }
            }

#pragma unroll
            for (int nt = 0; nt < 8; nt++) {
                sc[nt][0] *= scale; sc[nt][1] *= scale;
                sc[nt][2] *= scale; sc[nt][3] *= scale;
            }
            if (j0 + 63 > row0g) {
#pragma unroll
                for (int nt = 0; nt < 8; nt++) {
                    int c = j0 + nt * 8 + (tig << 1);
                    if (c > row0g)     sc[nt][0] = -1e30f;
                    if (c + 1 > row0g) sc[nt][1] = -1e30f;
                    if (c > row1g)     sc[nt][2] = -1e30f;
                    if (c + 1 > row1g) sc[nt][3] = -1e30f;
                }
            }

            float mx0 = -1e30f, mx1 = -1e30f;
#pragma unroll
            for (int nt = 0; nt < 8; nt++) {
                mx0 = fmaxf(mx0, fmaxf(sc[nt][0], sc[nt][1]));
                mx1 = fmaxf(mx1, fmaxf(sc[nt][2], sc[nt][3]));
            }
            mx0 = fmaxf(mx0, __shfl_xor_sync(0xffffffffu, mx0, 1));
            mx0 = fmaxf(mx0, __shfl_xor_sync(0xffffffffu, mx0, 2));
            mx1 = fmaxf(mx1, __shfl_xor_sync(0xffffffffu, mx1, 1));
            mx1 = fmaxf(mx1, __shfl_xor_sync(0xffffffffu, mx1, 2));

            float mn0 = fmaxf(m0, mx0), mn1 = fmaxf(m1, mx1);
            float al0 = __expf(m0 - mn0), al1 = __expf(m1 - mn1);
            m0 = mn0; m1 = mn1;

            float ps0 = 0.f, ps1 = 0.f;
#pragma unroll
            for (int nt = 0; nt < 8; nt++) {
                sc[nt][0] = __expf(sc[nt][0] - mn0);
                sc[nt][1] = __expf(sc[nt][1] - mn0);
                sc[nt][2] = __expf(sc[nt][2] - mn1);
                sc[nt][3] = __expf(sc[nt][3] - mn1);
                ps0 += sc[nt][0] + sc[nt][1];
                ps1 += sc[nt][2] + sc[nt][3];
            }
            ps0 += __shfl_xor_sync(0xffffffffu, ps0, 1);
            ps0 += __shfl_xor_sync(0xffffffffu, ps0, 2);
            ps1 += __shfl_xor_sync(0xffffffffu, ps1, 1);
            ps1 += __shfl_xor_sync(0xffffffffu, ps1, 2);
            l0 = l0 * al0 + ps0;
            l1 = l1 * al1 + ps1;

#pragma unroll
            for (int nt = 0; nt < 8; nt++) {
                oacc[nt][0] *= al0; oacc[nt][1] *= al0;
                oacc[nt][2] *= al1; oacc[nt][3] *= al1;
            }

            const int sL = tig >> 1;
            const bool odd = tig & 1;
#pragma unroll
            for (int ks = 0; ks < 8; ks++) {
                float a0 = __shfl_sync(0xffffffffu, sc[ks][0], sL, 4);
                float a1 = __shfl_sync(0xffffffffu, sc[ks][1], sL, 4);
                float b0 = __shfl_sync(0xffffffffu, sc[ks][0], sL + 2, 4);
                float b1 = __shfl_sync(0xffffffffu, sc[ks][1], sL + 2, 4);
                float c0 = __shfl_sync(0xffffffffu, sc[ks][2], sL, 4);
                float c1 = __shfl_sync(0xffffffffu, sc[ks][3], sL, 4);
                float d0 = __shfl_sync(0xffffffffu, sc[ks][2], sL + 2, 4);
                float d1 = __shfl_sync(0xffffffffu, sc[ks][3], sL + 2, 4);
                uint32_t pa[4];
                pa[0] = f2tf32u(odd ? a1 : a0);
                pa[1] = f2tf32u(odd ? c1 : c0);
                pa[2] = f2tf32u(odd ? b1 : b0);
                pa[3] = f2tf32u(odd ? d1 : d0);
#pragma unroll
                for (int nt = 0; nt < 8; nt++) {
                    uint2 vb = *(const uint2*)&Vb[((nt * 8 + ks) * 32 + lane) * 2];
                    MMA_TF32(oacc[nt], pa, vb);
                }
            }
        }
    }
#undef LOAD_KV

    // ---- epilogue: write O directly in A-fragment layout (tf32) ----
    float inv0 = 1.f / l0, inv1 = 1.f / l1;
    const int growA = b * TSEQ + row0g;
    const int growB = b * TSEQ + row1g;
    const int mtA = (growA & 127) >> 4, rmA = growA & 15;
    const int mtB = (growB & 127) >> 4, rmB = growB & 15;
    const size_t blkA = (size_t)(growA >> 7) * 32 * 4096;
    const size_t blkB = (size_t)(growB >> 7) * 32 * 4096;
#pragma unroll
    for (int nt = 0; nt < 8; nt++) {
        int col = h * DH + nt * 8 + (tig << 1);
        int chunk = col >> 5, ks = (col >> 3) & 3, e = col & 3;
        int regHi = (col >> 2) & 1;
        size_t iA = blkA + (size_t)chunk * 4096
                  + (((mtA * 4 + ks) * 32 + ((rmA & 7) << 2) + e) << 2)
                  + ((rmA >> 3) | (regHi << 1));
        size_t iB = blkB + (size_t)chunk * 4096
                  + (((mtB * 4 + ks) * 32 + ((rmB & 7) << 2) + e) << 2)
                  + ((rmB >> 3) | (regHi << 1));
        Op[iA]     = f2tf32f(oacc[nt][0] * inv0);
        Op[iA + 4] = f2tf32f(oacc[nt][1] * inv0);
        Op[iB]     = f2tf32f(oacc[nt][2] * inv1);
        Op[iB + 4] = f2tf32f(oacc[nt][3] * inv1);
    }
}

// ---------------------------------------------------------------------------
extern "C" void kernel_launch(void* const* d_in, const int* in_sizes, int n_in,
                              void* d_out, int out_size)
{
    (void)in_sizes; (void)n_in; (void)out_size;
    const float* x  = (const float*)d_in[0];
    const float* Wq = (const float*)d_in[1];
    // d_in[2] (W_k) intentionally unused: reference computes K with W_q
    const float* Wv = (const float*)d_in[3];
    const float* Wo = (const float*)d_in[4];
    float* out = (float*)d_out;

    float *Qb, *Vb, *Xp, *Op, *Wqp, *Wvp, *Wop;
    cudaGetSymbolAddress((void**)&Qb,  g_Q);
    cudaGetSymbolAddress((void**)&Vb,  g_V);
    cudaGetSymbolAddress((void**)&Xp,  g_Xp);
    cudaGetSymbolAddress((void**)&Op,  g_Op);
    cudaGetSymbolAddress((void**)&Wqp, g_Wqp);
    cudaGetSymbolAddress((void**)&Wvp, g_Wvp);
    cudaGetSymbolAddress((void**)&Wop, g_Wop);

    cudaFuncSetAttribute(attn_mma, cudaFuncAttributeMaxDynamicSharedMemorySize,
                         ATT_SMEM);

    // Pre-permute operands into fragment layouts (tf32)
    perm_w<<<1024, 256>>>(Wq, Wqp);
    perm_w<<<1024, 256>>>(Wv, Wvp);
    perm_w<<<1024, 256>>>(Wo, Wop);
    perm_x<<<8192, 256>>>(x, Xp);

    dim3 gg(CDIM / 128, MTOT / 128);  // (8, 64)
    gemm_frag<<<gg, 256>>>(Xp, Wqp, Qb);
    gemm_frag<<<gg, 256>>>(Xp, Wvp, Vb);

    attn_mma<<<dim3(TSEQ / 128, 4 * NHEAD), 256, ATT_SMEM>>>(Qb, Vb, Op);

    gemm_frag<<<gg, 256>>>(Op, Wop, out);
}